// round 8
// baseline (speedup 1.0000x reference)
#include <cuda_runtime.h>
#include <stdint.h>

#define B_   4
#define H_   8
#define N_   2048
#define DV_  64
#define BH_  (B_ * H_)            // 32
#define COLS_ (BH_ * DV_)         // 2048 sort columns
#define OUT_ELEMS (BH_ * (size_t)N_ * DV_)
#define ATTN_ELEMS ((size_t)BH_ * N_ * N_)

// ---------------- scratch ----------------------------------------------------
__device__ float    g_vs  [COLS_ * N_];   // sorted values [bh][d][r]
__device__ uint16_t g_inv [COLS_ * N_];   // rank of orig index i
__device__ uint16_t g_p0  [BH_  * N_];    // p_0[r]

__device__ __forceinline__ uint32_t f2sort(float x) {
    uint32_t u = __float_as_uint(x);
    return u ^ ((u & 0x80000000u) ? 0xFFFFFFFFu : 0x80000000u);
}
__device__ __forceinline__ float sort2f(uint32_t u) {
    u ^= (u & 0x80000000u) ? 0x80000000u : 0xFFFFFFFFu;
    return __uint_as_float(u);
}
__device__ __forceinline__ uint64_t cmpsel(uint64_t a, uint64_t y, bool keepmin) {
    return ((y < a) == keepmin) ? y : a;
}

// ---------------- bitonic merge tail, compile-time J -------------------------
// map: e = warp*256 + lane*8 + r
template<int J>
__device__ __forceinline__ void merge_tail(uint64_t* x, int lane, int warp, int k) {
    if constexpr (J >= 8) {
        constexpr int LJ = J / 8;
#pragma unroll
        for (int r = 0; r < 8; r++) {
            int e = warp * 256 + lane * 8 + r;
            uint64_t y = __shfl_xor_sync(0xffffffffu, x[r], LJ);
            bool keepmin = (((lane & LJ) == 0) == ((e & k) == 0));
            x[r] = cmpsel(x[r], y, keepmin);
        }
    } else {
#pragma unroll
        for (int r = 0; r < 8; r++) {
            if ((r & J) == 0) {
                int e = warp * 256 + lane * 8 + r;
                bool up = ((e & k) == 0);
                uint64_t a = x[r], c = x[r + J];
                uint64_t mn = a < c ? a : c;
                uint64_t mx = a < c ? c : a;
                x[r]     = up ? mn : mx;
                x[r + J] = up ? mx : mn;
            }
        }
    }
    if constexpr (J > 1) merge_tail<J / 2>(x, lane, warp, k);
}

// one cross-warp smem exchange stage (j >= 256)
__device__ __forceinline__ void smem_stage(uint64_t* x, uint64_t* s,
                                           int g, int ebase, int j, int k) {
#pragma unroll
    for (int r = 0; r < 8; r += 2)
        *reinterpret_cast<ulonglong2*>(&s[10 * g + r]) =
            make_ulonglong2(x[r], x[r + 1]);
    __syncthreads();
    const int gp = g ^ (j >> 3);
    const bool upperbit = ((g & (j >> 3)) == 0);
    const bool kbit     = ((ebase & k) == 0);
    const bool keepmin  = (upperbit == kbit);
    uint64_t y[8];
#pragma unroll
    for (int r = 0; r < 8; r += 2) {
        ulonglong2 t2 = *reinterpret_cast<const ulonglong2*>(&s[10 * gp + r]);
        y[r] = t2.x; y[r + 1] = t2.y;
    }
#pragma unroll
    for (int r = 0; r < 8; r++)
        x[r] = cmpsel(x[r], y[r], keepmin);
    __syncthreads();
}

// ---------------- 1) persistent fused sort + fill ----------------------------
// grid = 512 (one wave @ 4 blocks/SM). Block p sorts columns 4p..4p+3 and
// zero-fills 4 x 256KB of attn, spread across all 4 sorts. Keys loaded
// directly from v (stride-64; L2 serves 7/8 of sectors).
__global__ __launch_bounds__(256, 4) void k_sortfill(const float* __restrict__ v,
                                                     float* __restrict__ attn) {
    const int t    = threadIdx.x;
    const int lane = t & 31;
    const int warp = t >> 5;
    const int g    = warp * 32 + lane;
    const int ebase = g * 8;
    const float4 z = make_float4(0.f, 0.f, 0.f, 0.f);

    __shared__ uint64_t s[10 * 256];   // 20KB

    for (int sub = 0; sub < 4; sub++) {
        const int col = blockIdx.x * 4 + sub;
        const int d   = col & 63;
        const int bh  = col >> 6;

        float4* __restrict__ fbase =
            reinterpret_cast<float4*>(attn) + (size_t)col * 16384 + t;
#define FILL4(c)                                                     \
        {  _Pragma("unroll")                                         \
           for (int s_ = 0; s_ < 4; s_++)                            \
               __stcs(fbase + (c) * 1024 + s_ * 256, z); }

        FILL4(0)

        // direct strided key load: v[bh][e][d], e = ebase..ebase+7
        const float* __restrict__ vcol = v + (size_t)bh * N_ * DV_ + d;
        uint64_t x[8];
#pragma unroll
        for (int r = 0; r < 8; r++) {
            int e = ebase + r;
            uint32_t kk = f2sort(__ldg(vcol + (size_t)e * DV_));
            x[r] = ((uint64_t)kk << 32) | (uint32_t)e;   // unique => stable
        }

        merge_tail<1>  (x, lane, warp, 2);
        merge_tail<2>  (x, lane, warp, 4);
        merge_tail<4>  (x, lane, warp, 8);
        FILL4(1)
        merge_tail<8>  (x, lane, warp, 16);
        FILL4(2)
        merge_tail<16> (x, lane, warp, 32);
        FILL4(3)
        merge_tail<32> (x, lane, warp, 64);
        FILL4(4)
        merge_tail<64> (x, lane, warp, 128);
        FILL4(5)
        merge_tail<128>(x, lane, warp, 256);
        FILL4(6)

        smem_stage(x, s, g, ebase, 256, 512);
        FILL4(7)
        merge_tail<128>(x, lane, warp, 512);
        FILL4(8)
        smem_stage(x, s, g, ebase, 512, 1024);
        FILL4(9)
        smem_stage(x, s, g, ebase, 256, 1024);
        FILL4(10)
        merge_tail<128>(x, lane, warp, 1024);
        FILL4(11)
        smem_stage(x, s, g, ebase, 1024, 2048);
        FILL4(12)
        smem_stage(x, s, g, ebase, 512, 2048);
        FILL4(13)
        smem_stage(x, s, g, ebase, 256, 2048);
        FILL4(14)
        merge_tail<128>(x, lane, warp, 2048);
        FILL4(15)

        // epilogue: element e holds rank-e entry
        float*    __restrict__ vs  = g_vs  + (size_t)col * N_;
        uint16_t* __restrict__ inv = g_inv + (size_t)col * N_;
        {
            float4 f0 = make_float4(sort2f((uint32_t)(x[0] >> 32)),
                                    sort2f((uint32_t)(x[1] >> 32)),
                                    sort2f((uint32_t)(x[2] >> 32)),
                                    sort2f((uint32_t)(x[3] >> 32)));
            float4 f1 = make_float4(sort2f((uint32_t)(x[4] >> 32)),
                                    sort2f((uint32_t)(x[5] >> 32)),
                                    sort2f((uint32_t)(x[6] >> 32)),
                                    sort2f((uint32_t)(x[7] >> 32)));
            *reinterpret_cast<float4*>(vs + ebase)     = f0;
            *reinterpret_cast<float4*>(vs + ebase + 4) = f1;
        }
#pragma unroll
        for (int r = 0; r < 8; r++) {
            uint32_t idx = (uint32_t)x[r];
            inv[idx] = (uint16_t)(ebase + r);
            if (d == 0) g_p0[bh * N_ + ebase + r] = (uint16_t)idx;
        }
#undef FILL4
        if (sub < 3) __syncthreads();   // protect smem reuse across columns
    }
}

// ---------------- 2) fused gather+transpose (and attn scatter blocks) --------
__global__ __launch_bounds__(512) void k_gather_t(float* __restrict__ out,
                                                  float* __restrict__ attn) {
    if (blockIdx.y == BH_) {   // attn: attn[bh][i][ p0[inv1[i]] ] = 1
        int base = blockIdx.x * 8192;
        for (int m = threadIdx.x; m < 8192; m += 512) {
            int gid = base + m;
            int bh = gid >> 11;
            int i  = gid & (N_ - 1);
            int j    = g_inv[(size_t)(bh * DV_ + 1) * N_ + i];
            int aidx = g_p0[bh * N_ + j];
            attn[(size_t)gid * N_ + aidx] = 1.0f;
        }
        return;
    }
    const int bh = blockIdx.y;
    const int d0 = blockIdx.x * 8;
    const int t  = threadIdx.x;

    __shared__ float    svs [8 * N_];        // 64KB
    __shared__ uint16_t sinv[8][512 + 8];

#pragma unroll
    for (int d = 0; d < 8; d++)
        for (int i = t; i < N_; i += 512)
            svs[d * N_ + i] = g_vs[(size_t)(bh * DV_ + d0 + d) * N_ + i];

    const int dd = t & 7;
    const int iw = t >> 3;
    float* obase = out + (size_t)bh * N_ * DV_ + d0 + dd;

    for (int it = 0; it < 4; it++) {
        const int i0 = it * 512;
        __syncthreads();
#pragma unroll
        for (int d = 0; d < 8; d++) {
            int d1 = (d0 + d + 1) & 63;
            sinv[d][t] = g_inv[(size_t)(bh * DV_ + d1) * N_ + i0 + t];
        }
        __syncthreads();
#pragma unroll
        for (int rr = 0; rr < 8; rr++) {
            int ii = rr * 64 + iw;
            int rank = sinv[dd][ii];
            obase[(size_t)(i0 + ii) * DV_] = svs[dd * N_ + rank];
        }
    }
}

// ---------------- launch ------------------------------------------------------
extern "C" void kernel_launch(void* const* d_in, const int* in_sizes, int n_in,
                              void* d_out, int out_size) {
    (void)in_sizes; (void)n_in; (void)out_size;
    const float* v = (const float*)d_in[2];      // order: q, k, v
    float* out  = (float*)d_out;
    float* attn = out + OUT_ELEMS;

    k_sortfill <<<COLS_ / 4, 256>>>(v, attn);
    k_gather_t <<<dim3(8, BH_ + 1), 512>>>(out, attn);
}

// round 9
// speedup vs baseline: 1.0266x; 1.0266x over previous
#include <cuda_runtime.h>
#include <stdint.h>

#define B_   4
#define H_   8
#define N_   2048
#define DV_  64
#define BH_  (B_ * H_)            // 32
#define COLS_ (BH_ * DV_)         // 2048 sort columns
#define OUT_ELEMS (BH_ * (size_t)N_ * DV_)
#define ATTN_ELEMS ((size_t)BH_ * N_ * N_)

// ---------------- scratch ----------------------------------------------------
__device__ uint32_t g_key [COLS_ * N_];   // sortable v, [bh][d][i]
__device__ float    g_vs  [COLS_ * N_];   // sorted values [bh][d][r]
__device__ uint16_t g_inv [COLS_ * N_];   // rank of orig index i
__device__ uint16_t g_p0  [BH_  * N_];    // p_0[r]

__device__ __forceinline__ uint32_t f2sort(float x) {
    uint32_t u = __float_as_uint(x);
    return u ^ ((u & 0x80000000u) ? 0xFFFFFFFFu : 0x80000000u);
}
__device__ __forceinline__ float sort2f(uint32_t u) {
    u ^= (u & 0x80000000u) ? 0x80000000u : 0xFFFFFFFFu;
    return __uint_as_float(u);
}
__device__ __forceinline__ uint64_t cmpsel(uint64_t a, uint64_t y, bool keepmin) {
    return ((y < a) == keepmin) ? y : a;
}

// ---------------- 1) transpose v [bh][i][d] -> g_key [bh][d][i] --------------
__global__ void k_transpose_in(const float* __restrict__ v) {
    __shared__ float tile[32][33];
    int bh = blockIdx.z;
    int i0 = blockIdx.x * 32;
    int d0 = blockIdx.y * 32;
    int tx = threadIdx.x, ty = threadIdx.y;     // (32,8)
    const float* src = v + (size_t)bh * N_ * DV_;
#pragma unroll
    for (int r = 0; r < 32; r += 8)
        tile[ty + r][tx] = src[(size_t)(i0 + ty + r) * DV_ + (d0 + tx)];
    __syncthreads();
    uint32_t* dst = g_key + (size_t)bh * DV_ * N_;
#pragma unroll
    for (int r = 0; r < 32; r += 8)
        dst[(size_t)(d0 + ty + r) * N_ + (i0 + tx)] = f2sort(tile[tx][ty + r]);
}

// ---------------- bitonic merge tail, compile-time J -------------------------
// map: e = warp*256 + lane*8 + r
template<int J>
__device__ __forceinline__ void merge_tail(uint64_t* x, int lane, int warp, int k) {
    if constexpr (J >= 8) {
        constexpr int LJ = J / 8;
#pragma unroll
        for (int r = 0; r < 8; r++) {
            int e = warp * 256 + lane * 8 + r;
            uint64_t y = __shfl_xor_sync(0xffffffffu, x[r], LJ);
            bool keepmin = (((lane & LJ) == 0) == ((e & k) == 0));
            x[r] = cmpsel(x[r], y, keepmin);
        }
    } else {
#pragma unroll
        for (int r = 0; r < 8; r++) {
            if ((r & J) == 0) {
                int e = warp * 256 + lane * 8 + r;
                bool up = ((e & k) == 0);
                uint64_t a = x[r], c = x[r + J];
                uint64_t mn = a < c ? a : c;
                uint64_t mx = a < c ? c : a;
                x[r]     = up ? mn : mx;
                x[r + J] = up ? mx : mn;
            }
        }
    }
    if constexpr (J > 1) merge_tail<J / 2>(x, lane, warp, k);
}

// one cross-warp smem exchange stage (j >= 256)
__device__ __forceinline__ void smem_stage(uint64_t* x, uint64_t* s,
                                           int g, int ebase, int j, int k) {
#pragma unroll
    for (int r = 0; r < 8; r += 2)
        *reinterpret_cast<ulonglong2*>(&s[10 * g + r]) =
            make_ulonglong2(x[r], x[r + 1]);
    __syncthreads();
    const int gp = g ^ (j >> 3);
    const bool upperbit = ((g & (j >> 3)) == 0);
    const bool kbit     = ((ebase & k) == 0);
    const bool keepmin  = (upperbit == kbit);
    uint64_t y[8];
#pragma unroll
    for (int r = 0; r < 8; r += 2) {
        ulonglong2 t2 = *reinterpret_cast<const ulonglong2*>(&s[10 * gp + r]);
        y[r] = t2.x; y[r + 1] = t2.y;
    }
#pragma unroll
    for (int r = 0; r < 8; r++)
        x[r] = cmpsel(x[r], y[r], keepmin);
    __syncthreads();
}

// ---------------- 2) persistent fused sort + fill (coalesced keys) -----------
// grid = 512 (one balanced wave @ 4 blocks/SM). Block p sorts columns
// 4p..4p+3 (coalesced uint4 loads from g_key) and fills 4 x 256KB of attn,
// spread across all 4 sorts so store issue tracks DRAM drain the whole time.
__global__ __launch_bounds__(256, 4) void k_sortfill(float* __restrict__ attn) {
    const int t    = threadIdx.x;
    const int lane = t & 31;
    const int warp = t >> 5;
    const int g    = warp * 32 + lane;
    const int ebase = g * 8;
    const float4 z = make_float4(0.f, 0.f, 0.f, 0.f);

    __shared__ uint64_t s[10 * 256];   // 20KB

#pragma unroll 1
    for (int sub = 0; sub < 4; sub++) {
        const int col = blockIdx.x * 4 + sub;
        const int d   = col & 63;
        const int bh  = col >> 6;

        float4* __restrict__ fbase =
            reinterpret_cast<float4*>(attn) + (size_t)col * 16384 + t;
#define FILL4(c)                                                     \
        {  _Pragma("unroll")                                         \
           for (int s_ = 0; s_ < 4; s_++)                            \
               __stcs(fbase + (c) * 1024 + s_ * 256, z); }

        FILL4(0)

        const uint32_t* __restrict__ key = g_key + (size_t)col * N_;
        uint64_t x[8];
        {
            uint4 k0 = *reinterpret_cast<const uint4*>(key + ebase);
            uint4 k1 = *reinterpret_cast<const uint4*>(key + ebase + 4);
            x[0] = ((uint64_t)k0.x << 32) | (uint32_t)(ebase + 0);
            x[1] = ((uint64_t)k0.y << 32) | (uint32_t)(ebase + 1);
            x[2] = ((uint64_t)k0.z << 32) | (uint32_t)(ebase + 2);
            x[3] = ((uint64_t)k0.w << 32) | (uint32_t)(ebase + 3);
            x[4] = ((uint64_t)k1.x << 32) | (uint32_t)(ebase + 4);
            x[5] = ((uint64_t)k1.y << 32) | (uint32_t)(ebase + 5);
            x[6] = ((uint64_t)k1.z << 32) | (uint32_t)(ebase + 6);
            x[7] = ((uint64_t)k1.w << 32) | (uint32_t)(ebase + 7);
        }

        merge_tail<1>  (x, lane, warp, 2);
        merge_tail<2>  (x, lane, warp, 4);
        merge_tail<4>  (x, lane, warp, 8);
        FILL4(1)
        merge_tail<8>  (x, lane, warp, 16);
        FILL4(2)
        merge_tail<16> (x, lane, warp, 32);
        FILL4(3)
        merge_tail<32> (x, lane, warp, 64);
        FILL4(4)
        merge_tail<64> (x, lane, warp, 128);
        FILL4(5)
        merge_tail<128>(x, lane, warp, 256);
        FILL4(6)

        smem_stage(x, s, g, ebase, 256, 512);
        FILL4(7)
        merge_tail<128>(x, lane, warp, 512);
        FILL4(8)
        smem_stage(x, s, g, ebase, 512, 1024);
        FILL4(9)
        smem_stage(x, s, g, ebase, 256, 1024);
        FILL4(10)
        merge_tail<128>(x, lane, warp, 1024);
        FILL4(11)
        smem_stage(x, s, g, ebase, 1024, 2048);
        FILL4(12)
        smem_stage(x, s, g, ebase, 512, 2048);
        FILL4(13)
        smem_stage(x, s, g, ebase, 256, 2048);
        FILL4(14)
        merge_tail<128>(x, lane, warp, 2048);
        FILL4(15)

        // epilogue
        float*    __restrict__ vs  = g_vs  + (size_t)col * N_;
        uint16_t* __restrict__ inv = g_inv + (size_t)col * N_;
        {
            float4 f0 = make_float4(sort2f((uint32_t)(x[0] >> 32)),
                                    sort2f((uint32_t)(x[1] >> 32)),
                                    sort2f((uint32_t)(x[2] >> 32)),
                                    sort2f((uint32_t)(x[3] >> 32)));
            float4 f1 = make_float4(sort2f((uint32_t)(x[4] >> 32)),
                                    sort2f((uint32_t)(x[5] >> 32)),
                                    sort2f((uint32_t)(x[6] >> 32)),
                                    sort2f((uint32_t)(x[7] >> 32)));
            *reinterpret_cast<float4*>(vs + ebase)     = f0;
            *reinterpret_cast<float4*>(vs + ebase + 4) = f1;
        }
#pragma unroll
        for (int r = 0; r < 8; r++) {
            uint32_t idx = (uint32_t)x[r];
            inv[idx] = (uint16_t)(ebase + r);
            if (d == 0) g_p0[bh * N_ + ebase + r] = (uint16_t)idx;
        }
#undef FILL4
        if (sub < 3) __syncthreads();
    }
}

// ---------------- 3) fused gather+transpose (and attn scatter blocks) --------
__global__ __launch_bounds__(512) void k_gather_t(float* __restrict__ out,
                                                  float* __restrict__ attn) {
    if (blockIdx.y == BH_) {   // attn: attn[bh][i][ p0[inv1[i]] ] = 1
        int base = blockIdx.x * 8192;
        for (int m = threadIdx.x; m < 8192; m += 512) {
            int gid = base + m;
            int bh = gid >> 11;
            int i  = gid & (N_ - 1);
            int j    = g_inv[(size_t)(bh * DV_ + 1) * N_ + i];
            int aidx = g_p0[bh * N_ + j];
            attn[(size_t)gid * N_ + aidx] = 1.0f;
        }
        return;
    }
    const int bh = blockIdx.y;
    const int d0 = blockIdx.x * 8;
    const int t  = threadIdx.x;

    __shared__ float    svs [8 * N_];        // 64KB
    __shared__ uint16_t sinv[8][512 + 8];

#pragma unroll
    for (int d = 0; d < 8; d++)
        for (int i = t; i < N_; i += 512)
            svs[d * N_ + i] = g_vs[(size_t)(bh * DV_ + d0 + d) * N_ + i];

    const int dd = t & 7;
    const int iw = t >> 3;
    float* obase = out + (size_t)bh * N_ * DV_ + d0 + dd;

    for (int it = 0; it < 4; it++) {
        const int i0 = it * 512;
        __syncthreads();
#pragma unroll
        for (int d = 0; d < 8; d++) {
            int d1 = (d0 + d + 1) & 63;
            sinv[d][t] = g_inv[(size_t)(bh * DV_ + d1) * N_ + i0 + t];
        }
        __syncthreads();
#pragma unroll
        for (int rr = 0; rr < 8; rr++) {
            int ii = rr * 64 + iw;
            int rank = sinv[dd][ii];
            obase[(size_t)(i0 + ii) * DV_] = svs[dd * N_ + rank];
        }
    }
}

// ---------------- launch ------------------------------------------------------
extern "C" void kernel_launch(void* const* d_in, const int* in_sizes, int n_in,
                              void* d_out, int out_size) {
    (void)in_sizes; (void)n_in; (void)out_size;
    const float* v = (const float*)d_in[2];      // order: q, k, v
    float* out  = (float*)d_out;
    float* attn = out + OUT_ELEMS;

    k_transpose_in <<<dim3(N_ / 32, DV_ / 32, BH_), dim3(32, 8)>>>(v);
    k_sortfill     <<<COLS_ / 4, 256>>>(attn);
    k_gather_t     <<<dim3(8, BH_ + 1), 512>>>(out, attn);
}

// round 10
// speedup vs baseline: 1.3861x; 1.3502x over previous
#include <cuda_runtime.h>
#include <stdint.h>

#define B_   4
#define H_   8
#define N_   2048
#define DV_  64
#define BH_  (B_ * H_)            // 32
#define COLS_ (BH_ * DV_)         // 2048 sort columns
#define OUT_ELEMS (BH_ * (size_t)N_ * DV_)
#define ATTN_ELEMS ((size_t)BH_ * N_ * N_)

// ---------------- scratch ----------------------------------------------------
__device__ uint32_t g_key [COLS_ * N_];   // sortable v, [bh][d][i]
__device__ float    g_vs  [COLS_ * N_];   // sorted values [bh][d][r]
__device__ uint16_t g_inv [COLS_ * N_];   // rank of orig index i
__device__ uint16_t g_p0  [BH_  * N_];    // p_0[r]

__device__ __forceinline__ uint32_t f2sort(float x) {
    uint32_t u = __float_as_uint(x);
    return u ^ ((u & 0x80000000u) ? 0xFFFFFFFFu : 0x80000000u);
}
__device__ __forceinline__ float sort2f(uint32_t u) {
    u ^= (u & 0x80000000u) ? 0x80000000u : 0xFFFFFFFFu;
    return __uint_as_float(u);
}
__device__ __forceinline__ uint64_t cmpsel(uint64_t a, uint64_t y, bool keepmin) {
    return ((y < a) == keepmin) ? y : a;
}

// ---------------- 1) transpose v [bh][i][d] -> g_key [bh][d][i] --------------
__global__ void k_transpose_in(const float* __restrict__ v) {
    __shared__ float tile[32][33];
    int bh = blockIdx.z;
    int i0 = blockIdx.x * 32;
    int d0 = blockIdx.y * 32;
    int tx = threadIdx.x, ty = threadIdx.y;     // (32,8)
    const float* src = v + (size_t)bh * N_ * DV_;
#pragma unroll
    for (int r = 0; r < 32; r += 8)
        tile[ty + r][tx] = src[(size_t)(i0 + ty + r) * DV_ + (d0 + tx)];
    __syncthreads();
    uint32_t* dst = g_key + (size_t)bh * DV_ * N_;
#pragma unroll
    for (int r = 0; r < 32; r += 8)
        dst[(size_t)(d0 + ty + r) * N_ + (i0 + tx)] = f2sort(tile[tx][ty + r]);
}

// ---------------- bitonic merge tail, compile-time J -------------------------
// map: e = warp*256 + lane*8 + r
template<int J>
__device__ __forceinline__ void merge_tail(uint64_t* x, int lane, int warp, int k) {
    if constexpr (J >= 8) {
        constexpr int LJ = J / 8;
#pragma unroll
        for (int r = 0; r < 8; r++) {
            int e = warp * 256 + lane * 8 + r;
            uint64_t y = __shfl_xor_sync(0xffffffffu, x[r], LJ);
            bool keepmin = (((lane & LJ) == 0) == ((e & k) == 0));
            x[r] = cmpsel(x[r], y, keepmin);
        }
    } else {
#pragma unroll
        for (int r = 0; r < 8; r++) {
            if ((r & J) == 0) {
                int e = warp * 256 + lane * 8 + r;
                bool up = ((e & k) == 0);
                uint64_t a = x[r], c = x[r + J];
                uint64_t mn = a < c ? a : c;
                uint64_t mx = a < c ? c : a;
                x[r]     = up ? mn : mx;
                x[r + J] = up ? mx : mn;
            }
        }
    }
    if constexpr (J > 1) merge_tail<J / 2>(x, lane, warp, k);
}

// one cross-warp smem exchange stage (j >= 256)
__device__ __forceinline__ void smem_stage(uint64_t* x, uint64_t* s,
                                           int g, int ebase, int j, int k) {
#pragma unroll
    for (int r = 0; r < 8; r += 2)
        *reinterpret_cast<ulonglong2*>(&s[10 * g + r]) =
            make_ulonglong2(x[r], x[r + 1]);
    __syncthreads();
    const int gp = g ^ (j >> 3);
    const bool upperbit = ((g & (j >> 3)) == 0);
    const bool kbit     = ((ebase & k) == 0);
    const bool keepmin  = (upperbit == kbit);
    uint64_t y[8];
#pragma unroll
    for (int r = 0; r < 8; r += 2) {
        ulonglong2 t2 = *reinterpret_cast<const ulonglong2*>(&s[10 * gp + r]);
        y[r] = t2.x; y[r + 1] = t2.y;
    }
#pragma unroll
    for (int r = 0; r < 8; r++)
        x[r] = cmpsel(x[r], y[r], keepmin);
    __syncthreads();
}

// ---------------- 2) fused: bitonic sort + attn zero-fill (R7 structure) -----
__global__ __launch_bounds__(256) void k_sortfill(float* __restrict__ attn) {
    const int col  = blockIdx.x;
    const int t    = threadIdx.x;
    const int lane = t & 31;
    const int warp = t >> 5;
    const int g    = warp * 32 + lane;
    const int ebase = g * 8;

    float4* __restrict__ fbase =
        reinterpret_cast<float4*>(attn) + (size_t)col * 16384 + t;
    const float4 z = make_float4(0.f, 0.f, 0.f, 0.f);
#define FILL4(c)                                                     \
    {  _Pragma("unroll")                                             \
       for (int s_ = 0; s_ < 4; s_++)                                \
           __stcs(fbase + (c) * 1024 + s_ * 256, z); }

    const uint32_t* __restrict__ key = g_key + (size_t)col * N_;

    FILL4(0)

    uint64_t x[8];
    {
        uint4 k0 = *reinterpret_cast<const uint4*>(key + ebase);
        uint4 k1 = *reinterpret_cast<const uint4*>(key + ebase + 4);
        x[0] = ((uint64_t)k0.x << 32) | (uint32_t)(ebase + 0);
        x[1] = ((uint64_t)k0.y << 32) | (uint32_t)(ebase + 1);
        x[2] = ((uint64_t)k0.z << 32) | (uint32_t)(ebase + 2);
        x[3] = ((uint64_t)k0.w << 32) | (uint32_t)(ebase + 3);
        x[4] = ((uint64_t)k1.x << 32) | (uint32_t)(ebase + 4);
        x[5] = ((uint64_t)k1.y << 32) | (uint32_t)(ebase + 5);
        x[6] = ((uint64_t)k1.z << 32) | (uint32_t)(ebase + 6);
        x[7] = ((uint64_t)k1.w << 32) | (uint32_t)(ebase + 7);
    }

    __shared__ uint64_t s[10 * 256];   // 20KB, stride-10 groups

    merge_tail<1>  (x, lane, warp, 2);
    merge_tail<2>  (x, lane, warp, 4);
    merge_tail<4>  (x, lane, warp, 8);
    FILL4(1)
    merge_tail<8>  (x, lane, warp, 16);
    FILL4(2)
    merge_tail<16> (x, lane, warp, 32);
    FILL4(3)
    merge_tail<32> (x, lane, warp, 64);
    FILL4(4)
    merge_tail<64> (x, lane, warp, 128);
    FILL4(5)
    merge_tail<128>(x, lane, warp, 256);
    FILL4(6)

    smem_stage(x, s, g, ebase, 256, 512);
    FILL4(7)
    merge_tail<128>(x, lane, warp, 512);
    FILL4(8)
    smem_stage(x, s, g, ebase, 512, 1024);
    FILL4(9)
    smem_stage(x, s, g, ebase, 256, 1024);
    FILL4(10)
    merge_tail<128>(x, lane, warp, 1024);
    FILL4(11)
    smem_stage(x, s, g, ebase, 1024, 2048);
    FILL4(12)
    smem_stage(x, s, g, ebase, 512, 2048);
    FILL4(13)
    smem_stage(x, s, g, ebase, 256, 2048);
    FILL4(14)
    merge_tail<128>(x, lane, warp, 2048);
    FILL4(15)

    // epilogue: element e holds rank-e entry
    const int d  = col & 63;
    const int bh = col >> 6;
    float*    __restrict__ vs  = g_vs  + (size_t)col * N_;
    uint16_t* __restrict__ inv = g_inv + (size_t)col * N_;
    {
        float4 f0 = make_float4(sort2f((uint32_t)(x[0] >> 32)),
                                sort2f((uint32_t)(x[1] >> 32)),
                                sort2f((uint32_t)(x[2] >> 32)),
                                sort2f((uint32_t)(x[3] >> 32)));
        float4 f1 = make_float4(sort2f((uint32_t)(x[4] >> 32)),
                                sort2f((uint32_t)(x[5] >> 32)),
                                sort2f((uint32_t)(x[6] >> 32)),
                                sort2f((uint32_t)(x[7] >> 32)));
        *reinterpret_cast<float4*>(vs + ebase)     = f0;
        *reinterpret_cast<float4*>(vs + ebase + 4) = f1;
    }
#pragma unroll
    for (int r = 0; r < 8; r++) {
        uint32_t idx = (uint32_t)x[r];
        inv[idx] = (uint16_t)(ebase + r);
        if (d == 0) g_p0[bh * N_ + ebase + r] = (uint16_t)idx;
    }
#undef FILL4
}

// ---------------- 3) gather+transpose, 4 d/block for occupancy ---------------
// grid (16, 33): y<32 -> gather (bh=y, d-group=x*4); y==32 -> attn scatter.
// 32KB svs + 4KB sinv per block -> ~6 resident blocks/SM (vs 3 with 8 d).
__global__ __launch_bounds__(512) void k_gather_t(float* __restrict__ out,
                                                  float* __restrict__ attn) {
    if (blockIdx.y == BH_) {   // attn: attn[bh][i][ p0[inv1[i]] ] = 1
        int base = blockIdx.x * 4096;
        for (int m = threadIdx.x; m < 4096; m += 512) {
            int gid = base + m;
            int bh = gid >> 11;
            int i  = gid & (N_ - 1);
            int j    = g_inv[(size_t)(bh * DV_ + 1) * N_ + i];
            int aidx = g_p0[bh * N_ + j];
            attn[(size_t)gid * N_ + aidx] = 1.0f;
        }
        return;
    }
    const int bh = blockIdx.y;
    const int d0 = blockIdx.x * 4;
    const int t  = threadIdx.x;

    __shared__ float    svs [4 * N_];        // 32KB
    __shared__ uint16_t sinv[4][512 + 8];    // 4.06KB

#pragma unroll
    for (int d = 0; d < 4; d++)
        for (int i = t; i < N_; i += 512)
            svs[d * N_ + i] = g_vs[(size_t)(bh * DV_ + d0 + d) * N_ + i];

    const int dd = t & 3;          // this thread's d
    const int iw = t >> 2;         // 0..127
    float* obase = out + (size_t)bh * N_ * DV_ + d0 + dd;

    for (int it = 0; it < 4; it++) {         // i-tiles of 512
        const int i0 = it * 512;
        __syncthreads();
#pragma unroll
        for (int d = 0; d < 4; d++) {
            int d1 = (d0 + d + 1) & 63;
            sinv[d][t] = g_inv[(size_t)(bh * DV_ + d1) * N_ + i0 + t];
        }
        __syncthreads();
#pragma unroll
        for (int rr = 0; rr < 4; rr++) {
            int ii = rr * 128 + iw;
            int rank = sinv[dd][ii];
            obase[(size_t)(i0 + ii) * DV_] = svs[dd * N_ + rank];
        }
    }
}

// ---------------- launch ------------------------------------------------------
extern "C" void kernel_launch(void* const* d_in, const int* in_sizes, int n_in,
                              void* d_out, int out_size) {
    (void)in_sizes; (void)n_in; (void)out_size;
    const float* v = (const float*)d_in[2];      // order: q, k, v
    float* out  = (float*)d_out;
    float* attn = out + OUT_ELEMS;

    k_transpose_in <<<dim3(N_ / 32, DV_ / 32, BH_), dim3(32, 8)>>>(v);
    k_sortfill     <<<COLS_, 256>>>(attn);
    k_gather_t     <<<dim3(16, BH_ + 1), 512>>>(out, attn);
}